// round 3
// baseline (speedup 1.0000x reference)
#include <cuda_runtime.h>

#define NBATCH 16
#define PPIX   (640*640)      // 409600 pixels per image
#define NCHUNK (PPIX/4)       // 102400 4-pixel chunks per image

// ---------------- device-global scratch (no allocations allowed) -------------
__device__ float  g_sum[NBATCH][8][4];   // kernel-region emb sums per label
__device__ float  g_ck [NBATCH][8];      // kernel-region counts per label
__device__ float  g_ci [NBATCH][8];      // instance-region counts per label
__device__ float4 g_mu [NBATCH][8];      // per-label means
__device__ float  g_w  [NBATCH][8];      // per-label aggregation weights
__device__ float  g_misc[NBATCH];        // l_dis + l_reg per batch
__device__ float  g_loss;                // accumulated weighted agg term

__device__ __forceinline__ float wredf(float v) {
#pragma unroll
    for (int o = 16; o; o >>= 1) v += __shfl_xor_sync(0xffffffffu, v, o);
    return v;
}

__device__ __forceinline__ float fsqrt_ap(float x) {
    float r;
    asm("sqrt.approx.f32 %0, %1;" : "=f"(r) : "f"(x));
    return r;
}

// predicated packed-f32x2 accumulate: if (lak==l) { slo+=elo; shi+=ehi; }
__device__ __forceinline__ void acc_label(unsigned long long& slo, unsigned long long& shi,
                                          unsigned long long elo, unsigned long long ehi,
                                          int lak, int l) {
    asm volatile(
        "{\n\t.reg .pred p;\n\t"
        "setp.eq.s32 p, %2, %3;\n\t"
        "@p add.rn.f32x2 %0, %0, %4;\n\t"
        "@p add.rn.f32x2 %1, %1, %5;\n\t}"
        : "+l"(slo), "+l"(shi)
        : "r"(lak), "r"(l), "l"(elo), "l"(ehi));
}

__device__ __forceinline__ float u64_lo_f(unsigned long long v) {
    return __uint_as_float((unsigned)(v & 0xffffffffull));
}
__device__ __forceinline__ float u64_hi_f(unsigned long long v) {
    return __uint_as_float((unsigned)(v >> 32));
}

// ---------------- kernel 0: zero accumulators --------------------------------
__global__ void k_zero() {
    int t = threadIdx.x;
    if (t < 512) (&g_sum[0][0][0])[t] = 0.f;
    if (t < 128) {
        (&g_ck[0][0])[t] = 0.f;
        (&g_ci[0][0])[t] = 0.f;
    }
    if (t == 0) g_loss = 0.f;
}

// ---------------- pass 1: segment sums/counts (pipelined, packed math) -------
#define PASS1_PX(LAB, KV, TV, ELO, EHI)                                   \
    {                                                                     \
        int la  = ((TV) > 0.5f) ? ((LAB) & 7) : 0;                        \
        int lak = ((KV) > 0.5f) ? la : 0;                                 \
        ci64 += 1ull << (8 * la);                                         \
        ck64 += 1ull << (8 * lak);                                        \
        _Pragma("unroll")                                                 \
        for (int l = 1; l < 8; l++)                                       \
            acc_label(s[l-1][0], s[l-1][1], (ELO), (EHI), lak, l);        \
    }

__global__ __launch_bounds__(256)
void k_pass1(const ulonglong2* __restrict__ emb, const int4* __restrict__ inst,
             const float4* __restrict__ ker, const float4* __restrict__ tmk) {
    const int b = blockIdx.y;
    unsigned long long s[7][2];
#pragma unroll
    for (int l = 0; l < 7; l++) { s[l][0] = 0ull; s[l][1] = 0ull; }
    unsigned long long ck64 = 0ull, ci64 = 0ull;

    const size_t base   = (size_t)b * NCHUNK;
    const int    stride = gridDim.x * blockDim.x;

    int m = blockIdx.x * blockDim.x + threadIdx.x;   // stride < NCHUNK guaranteed
    int4   iv = inst[base + m];
    float4 kv = ker [base + m];
    float4 tv = tmk [base + m];
    const ulonglong2* ep = emb + ((base + (size_t)m) << 1);
    ulonglong2 ea = ep[0], eb = ep[1];               // 4 px = (x,y)(z,w) ×2... per-pixel pairs below

    // layout: chunk holds px0=(ea.x lo2ch, ea.y hi2ch)... actually:
    // float4 px0 = bytes[0:16) -> ulonglong2 ep[0] = {px0.xy, px0.zw}
    // float4 px1 = bytes[16:32) -> ep[1] = {px1.xy, px1.zw}
    const ulonglong2* ep2 = ep + 2;
    ulonglong2 ec = ep2[0], ed = ep2[1];             // px2, px3

    for (;;) {
        const int  mn  = m + stride;
        const bool has = (mn < NCHUNK);
        const int  ms  = has ? mn : m;
        int4   ivn = inst[base + ms];
        float4 kvn = ker [base + ms];
        float4 tvn = tmk [base + ms];
        const ulonglong2* en = emb + ((base + (size_t)ms) << 1);
        ulonglong2 na = en[0], nb = en[1], nc = en[2], nd = en[3];

        PASS1_PX(iv.x, kv.x, tv.x, ea.x, ea.y);
        PASS1_PX(iv.y, kv.y, tv.y, eb.x, eb.y);
        PASS1_PX(iv.z, kv.z, tv.z, ec.x, ec.y);
        PASS1_PX(iv.w, kv.w, tv.w, ed.x, ed.y);

        if (!has) break;
        iv = ivn; kv = kvn; tv = tvn;
        ea = na; eb = nb; ec = nc; ed = nd;
        m = mn;
    }

    const unsigned lane = threadIdx.x & 31u;
#pragma unroll
    for (int l = 0; l < 7; l++) {
        float v0 = wredf(u64_lo_f(s[l][0]));
        float v1 = wredf(u64_hi_f(s[l][0]));
        float v2 = wredf(u64_lo_f(s[l][1]));
        float v3 = wredf(u64_hi_f(s[l][1]));
        if (lane == 0) {
            atomicAdd(&g_sum[b][l+1][0], v0);
            atomicAdd(&g_sum[b][l+1][1], v1);
            atomicAdd(&g_sum[b][l+1][2], v2);
            atomicAdd(&g_sum[b][l+1][3], v3);
        }
    }
#pragma unroll
    for (int l = 1; l < 8; l++) {
        float v = wredf((float)((ck64 >> (8*l)) & 255ull));
        if (lane == 0) atomicAdd(&g_ck[b][l], v);
    }
#pragma unroll
    for (int l = 2; l < 8; l++) {
        float v = wredf((float)((ci64 >> (8*l)) & 255ull));
        if (lane == 0) atomicAdd(&g_ci[b][l], v);
    }
}

// ---------------- mid kernel: mu, weights, discrimination + reg --------------
__global__ void k_mid() {
    __shared__ float4 smu[NBATCH][8];
    int t = threadIdx.x;
    if (t < 128) {
        int b = t >> 3, l = t & 7;
        float4 mu = make_float4(0.f, 0.f, 0.f, 0.f);
        if (l > 0) {
            float c = fmaxf(g_ck[b][l], 1.f);
            mu.x = g_sum[b][l][0] / c;
            mu.y = g_sum[b][l][1] / c;
            mu.z = g_sum[b][l][2] / c;
            mu.w = g_sum[b][l][3] / c;
        }
        smu[b][l] = mu;
        g_mu[b][l] = mu;
        float w = 0.f;
        if (l >= 2) w = 1.0f / (96.0f * fmaxf(g_ci[b][l], 1.f));
        g_w[b][l] = w;
    }
    __syncthreads();
    if (t < NBATCH) {
        int b = t;
        float dis = 0.f;
        for (int i = 1; i < 8; i++) {
            float4 a = smu[b][i];
            for (int j = 1; j < 8; j++) {
                if (j == i) continue;
                float4 c = smu[b][j];
                float dx = a.x - c.x, dy = a.y - c.y, dz = a.z - c.z, dw = a.w - c.w;
                float sq = dx*dx + dy*dy + dz*dz + dw*dw;
                float dd = sqrtf(sq);
                float x  = fmaxf(3.0f - dd, 0.f);     // 2*DELTA_D - dd
                dis += logf(fmaf(x, x, 1.f));
            }
        }
        dis *= (1.0f / 42.0f);
        float reg = 0.f;
        for (int l = 0; l < 8; l++) {
            float4 a = smu[b][l];
            float n = sqrtf(a.x*a.x + a.y*a.y + a.z*a.z + a.w*a.w);
            reg += logf(n + 1.f);
        }
        reg *= (0.001f / 8.0f);
        g_misc[b] = dis + reg;
    }
}

// ---------------- pass 2: aggregation term (pipelined) -----------------------
#define PASS2_PX(LAB, TV, EV, ACC)                                         \
    {                                                                      \
        int la = ((TV) > 0.5f) ? ((LAB) & 7) : 0;                          \
        float4 mm = smu[la];                                               \
        float  w  = sw[la];                                                \
        float dx = (EV).x - mm.x, dy = (EV).y - mm.y;                      \
        float dz = (EV).z - mm.z, dw = (EV).w - mm.w;                      \
        float sq = fmaf(dx, dx, fmaf(dy, dy, fmaf(dz, dz, dw*dw)));       \
        float d  = fsqrt_ap(sq);                                           \
        float x  = fmaxf(d - 0.5f, 0.f);                                   \
        ACC = fmaf(__logf(fmaf(x, x, 1.f)), w, ACC);                       \
    }

__global__ __launch_bounds__(256)
void k_pass2(const float4* __restrict__ emb, const int4* __restrict__ inst,
             const float4* __restrict__ tmk) {
    const int b = blockIdx.y;
    __shared__ float4 smu[8];
    __shared__ float  sw[8];
    if (threadIdx.x < 8) {
        smu[threadIdx.x] = g_mu[b][threadIdx.x];
        sw [threadIdx.x] = g_w [b][threadIdx.x];
    }
    __syncthreads();

    const size_t base   = (size_t)b * NCHUNK;
    const int    stride = gridDim.x * blockDim.x;

    // reversed traversal: first iterations hit pass1's L2-resident tail
    int m = (NCHUNK - 1) - (blockIdx.x * blockDim.x + threadIdx.x);
    int4   iv = inst[base + m];
    float4 tv = tmk [base + m];
    const float4* ep = emb + ((base + (size_t)m) << 2);
    float4 e0 = ep[0], e1 = ep[1], e2 = ep[2], e3 = ep[3];

    float acc0 = 0.f, acc1 = 0.f;
    for (;;) {
        const int  mn  = m - stride;
        const bool has = (mn >= 0);
        const int  ms  = has ? mn : m;
        int4   ivn = inst[base + ms];
        float4 tvn = tmk [base + ms];
        const float4* en = emb + ((base + (size_t)ms) << 2);
        float4 n0 = en[0], n1 = en[1], n2 = en[2], n3 = en[3];

        PASS2_PX(iv.x, tv.x, e0, acc0);
        PASS2_PX(iv.y, tv.y, e1, acc1);
        PASS2_PX(iv.z, tv.z, e2, acc0);
        PASS2_PX(iv.w, tv.w, e3, acc1);

        if (!has) break;
        iv = ivn; tv = tvn;
        e0 = n0; e1 = n1; e2 = n2; e3 = n3;
        m = mn;
    }

    float v = wredf(acc0 + acc1);
    if ((threadIdx.x & 31u) == 0) atomicAdd(&g_loss, v);
}

// ---------------- finalize ---------------------------------------------------
__global__ void k_fin(float* out) {
    if (threadIdx.x == 0) {
        float misc = 0.f;
        for (int b = 0; b < NBATCH; b++) misc += g_misc[b];
        out[0] = g_loss + misc * (1.0f / 16.0f);
    }
}

// ---------------- launch -----------------------------------------------------
static int pick_gx(int occ, int nsm) {
    if (occ < 1) occ = 1;
    long gx = (long)occ * nsm / NBATCH;          // fill one full occupancy wave
    if (gx < 8)   gx = 8;                        // count-field overflow guard
    if (gx > 400) gx = 400;
    return (int)gx;
}

extern "C" void kernel_launch(void* const* d_in, const int* in_sizes, int n_in,
                              void* d_out, int out_size) {
    (void)in_sizes; (void)n_in; (void)out_size;
    const float4* emb  = (const float4*)d_in[0];
    const int4*   inst = (const int4*)  d_in[1];
    const float4* ker  = (const float4*)d_in[2];
    const float4* tmk  = (const float4*)d_in[3];
    float*        out  = (float*)d_out;

    int nsm = 152;
    cudaDeviceGetAttribute(&nsm, cudaDevAttrMultiProcessorCount, 0);
    int occ1 = 0, occ2 = 0;
    cudaOccupancyMaxActiveBlocksPerMultiprocessor(&occ1, k_pass1, 256, 0);
    cudaOccupancyMaxActiveBlocksPerMultiprocessor(&occ2, k_pass2, 256, 0);
    int gx1 = pick_gx(occ1, nsm);
    int gx2 = pick_gx(occ2, nsm);

    k_zero<<<1, 512>>>();
    k_pass1<<<dim3(gx1, NBATCH), 256>>>((const ulonglong2*)emb, inst, ker, tmk);
    k_mid<<<1, 128>>>();
    k_pass2<<<dim3(gx2, NBATCH), 256>>>(emb, inst, tmk);
    k_fin<<<1, 32>>>(out);
}

// round 4
// speedup vs baseline: 1.1621x; 1.1621x over previous
#include <cuda_runtime.h>

#define NBATCH 16
#define PPIX   (640*640)      // 409600 pixels per image
#define NCHUNK (PPIX/4)       // 102400 4-pixel chunks per image

// ---------------- device-global scratch (no allocations allowed) -------------
__device__ float  g_sum[NBATCH][8][4];   // kernel-region emb sums per label
__device__ float  g_ck [NBATCH][8];      // kernel-region counts per label
__device__ float  g_ci [NBATCH][8];      // instance-region counts per label
__device__ float4 g_mu [NBATCH][8];      // per-label means
__device__ float  g_w  [NBATCH][8];      // per-label aggregation weights
__device__ float  g_misc[NBATCH];        // l_dis + l_reg per batch
__device__ float  g_loss;                // accumulated weighted agg term

__device__ __forceinline__ float wredf(float v) {
#pragma unroll
    for (int o = 16; o; o >>= 1) v += __shfl_xor_sync(0xffffffffu, v, o);
    return v;
}

__device__ __forceinline__ float fsqrt_ap(float x) {
    float r;
    asm("sqrt.approx.f32 %0, %1;" : "=f"(r) : "f"(x));
    return r;
}

// predicated packed-f32x2 accumulate: if (lak==l) { slo+=elo; shi+=ehi; }
// NOTE: non-volatile — pure register ops, lets NVVM/ptxas schedule loads around it.
__device__ __forceinline__ void acc_label(unsigned long long& slo, unsigned long long& shi,
                                          unsigned long long elo, unsigned long long ehi,
                                          int lak, int l) {
    asm("{\n\t.reg .pred p;\n\t"
        "setp.eq.s32 p, %2, %3;\n\t"
        "@p add.rn.f32x2 %0, %0, %4;\n\t"
        "@p add.rn.f32x2 %1, %1, %5;\n\t}"
        : "+l"(slo), "+l"(shi)
        : "r"(lak), "r"(l), "l"(elo), "l"(ehi));
}

__device__ __forceinline__ float u64_lo_f(unsigned long long v) {
    return __uint_as_float((unsigned)(v & 0xffffffffull));
}
__device__ __forceinline__ float u64_hi_f(unsigned long long v) {
    return __uint_as_float((unsigned)(v >> 32));
}

// ---------------- kernel 0: zero accumulators --------------------------------
__global__ void k_zero() {
    int t = threadIdx.x;
    if (t < 512) (&g_sum[0][0][0])[t] = 0.f;
    if (t < 128) {
        (&g_ck[0][0])[t] = 0.f;
        (&g_ci[0][0])[t] = 0.f;
    }
    if (t == 0) g_loss = 0.f;
}

// ---------------- pass 1: segment sums/counts (pipelined, packed math) -------
// counts: 8-bit fields of one u64 per histogram; max hits/field = 4*iters <= 200 < 255
#define PASS1_PX(LAB, KV, TV, ELO, EHI)                                   \
    {                                                                     \
        int la  = ((TV) > 0.5f) ? ((LAB) & 7) : 0;                        \
        int lak = ((KV) > 0.5f) ? la : 0;                                 \
        ci64 += 1ull << (8 * la);                                         \
        ck64 += 1ull << (8 * lak);                                        \
        _Pragma("unroll")                                                 \
        for (int l = 1; l < 8; l++)                                       \
            acc_label(s[l-1][0], s[l-1][1], (ELO), (EHI), lak, l);        \
    }

__global__ __launch_bounds__(256)
void k_pass1(const ulonglong2* __restrict__ emb, const int4* __restrict__ inst,
             const float4* __restrict__ ker, const float4* __restrict__ tmk) {
    const int b = blockIdx.y;
    unsigned long long s[7][2];
#pragma unroll
    for (int l = 0; l < 7; l++) { s[l][0] = 0ull; s[l][1] = 0ull; }
    unsigned long long ck64 = 0ull, ci64 = 0ull;

    const size_t base   = (size_t)b * NCHUNK;
    const int    stride = gridDim.x * blockDim.x;
    const int    iters  = NCHUNK / stride;          // exact (grid is a divisor)

    int m = blockIdx.x * blockDim.x + threadIdx.x;
    int4   iv = inst[base + m];
    float4 kv = ker [base + m];
    float4 tv = tmk [base + m];
    const ulonglong2* ep = emb + ((base + (size_t)m) << 1);
    // chunk = 4 float4 pixels = 4 ulonglong2: {px0.xy,px0.zw},{px1.xy,px1.zw},...
    ulonglong2 ea = ep[0], eb = ep[1], ec = ep[2], ed = ep[3];

    for (int it = 1; it < iters; it++) {
        const int mn = m + stride;
        int4   ivn = inst[base + mn];
        float4 kvn = ker [base + mn];
        float4 tvn = tmk [base + mn];
        const ulonglong2* en = emb + ((base + (size_t)mn) << 1);
        ulonglong2 na = en[0], nb = en[1], nc = en[2], nd = en[3];

        PASS1_PX(iv.x, kv.x, tv.x, ea.x, ea.y);
        PASS1_PX(iv.y, kv.y, tv.y, eb.x, eb.y);
        PASS1_PX(iv.z, kv.z, tv.z, ec.x, ec.y);
        PASS1_PX(iv.w, kv.w, tv.w, ed.x, ed.y);

        iv = ivn; kv = kvn; tv = tvn;
        ea = na; eb = nb; ec = nc; ed = nd;
        m = mn;
    }
    PASS1_PX(iv.x, kv.x, tv.x, ea.x, ea.y);
    PASS1_PX(iv.y, kv.y, tv.y, eb.x, eb.y);
    PASS1_PX(iv.z, kv.z, tv.z, ec.x, ec.y);
    PASS1_PX(iv.w, kv.w, tv.w, ed.x, ed.y);

    const unsigned lane = threadIdx.x & 31u;
#pragma unroll
    for (int l = 0; l < 7; l++) {
        float v0 = wredf(u64_lo_f(s[l][0]));
        float v1 = wredf(u64_hi_f(s[l][0]));
        float v2 = wredf(u64_lo_f(s[l][1]));
        float v3 = wredf(u64_hi_f(s[l][1]));
        if (lane == 0) {
            atomicAdd(&g_sum[b][l+1][0], v0);
            atomicAdd(&g_sum[b][l+1][1], v1);
            atomicAdd(&g_sum[b][l+1][2], v2);
            atomicAdd(&g_sum[b][l+1][3], v3);
        }
    }
#pragma unroll
    for (int l = 1; l < 8; l++) {
        float v = wredf((float)((ck64 >> (8*l)) & 255ull));
        if (lane == 0) atomicAdd(&g_ck[b][l], v);
    }
#pragma unroll
    for (int l = 2; l < 8; l++) {
        float v = wredf((float)((ci64 >> (8*l)) & 255ull));
        if (lane == 0) atomicAdd(&g_ci[b][l], v);
    }
}

// ---------------- mid kernel: mu, weights, discrimination + reg --------------
__global__ void k_mid() {
    __shared__ float4 smu[NBATCH][8];
    int t = threadIdx.x;
    if (t < 128) {
        int b = t >> 3, l = t & 7;
        float4 mu = make_float4(0.f, 0.f, 0.f, 0.f);
        if (l > 0) {
            float c = fmaxf(g_ck[b][l], 1.f);
            mu.x = g_sum[b][l][0] / c;
            mu.y = g_sum[b][l][1] / c;
            mu.z = g_sum[b][l][2] / c;
            mu.w = g_sum[b][l][3] / c;
        }
        smu[b][l] = mu;
        g_mu[b][l] = mu;
        float w = 0.f;
        if (l >= 2) w = 1.0f / (96.0f * fmaxf(g_ci[b][l], 1.f));
        g_w[b][l] = w;
    }
    __syncthreads();
    if (t < NBATCH) {
        int b = t;
        float dis = 0.f;
        for (int i = 1; i < 8; i++) {
            float4 a = smu[b][i];
            for (int j = 1; j < 8; j++) {
                if (j == i) continue;
                float4 c = smu[b][j];
                float dx = a.x - c.x, dy = a.y - c.y, dz = a.z - c.z, dw = a.w - c.w;
                float sq = dx*dx + dy*dy + dz*dz + dw*dw;
                float dd = sqrtf(sq);
                float x  = fmaxf(3.0f - dd, 0.f);     // 2*DELTA_D - dd
                dis += logf(fmaf(x, x, 1.f));
            }
        }
        dis *= (1.0f / 42.0f);
        float reg = 0.f;
        for (int l = 0; l < 8; l++) {
            float4 a = smu[b][l];
            float n = sqrtf(a.x*a.x + a.y*a.y + a.z*a.z + a.w*a.w);
            reg += logf(n + 1.f);
        }
        reg *= (0.001f / 8.0f);
        g_misc[b] = dis + reg;
    }
}

// ---------------- pass 2: aggregation term (pipelined, exact iters) ----------
#define PASS2_PX(LAB, TV, EV, ACC)                                         \
    {                                                                      \
        int la = ((TV) > 0.5f) ? ((LAB) & 7) : 0;                          \
        float4 mm = smu[la];                                               \
        float  w  = sw[la];                                                \
        float dx = (EV).x - mm.x, dy = (EV).y - mm.y;                      \
        float dz = (EV).z - mm.z, dw = (EV).w - mm.w;                      \
        float sq = fmaf(dx, dx, fmaf(dy, dy, fmaf(dz, dz, dw*dw)));       \
        float d  = fsqrt_ap(sq);                                           \
        float x  = fmaxf(d - 0.5f, 0.f);                                   \
        ACC = fmaf(__logf(fmaf(x, x, 1.f)), w, ACC);                       \
    }

__global__ __launch_bounds__(256)
void k_pass2(const float4* __restrict__ emb, const int4* __restrict__ inst,
             const float4* __restrict__ tmk) {
    const int b = blockIdx.y;
    __shared__ float4 smu[8];
    __shared__ float  sw[8];
    if (threadIdx.x < 8) {
        smu[threadIdx.x] = g_mu[b][threadIdx.x];
        sw [threadIdx.x] = g_w [b][threadIdx.x];
    }
    __syncthreads();

    const size_t base   = (size_t)b * NCHUNK;
    const int    stride = gridDim.x * blockDim.x;
    const int    iters  = NCHUNK / stride;          // exact

    // reversed traversal: first iterations hit pass1's L2-resident tail
    int m = (NCHUNK - 1) - (blockIdx.x * blockDim.x + threadIdx.x);
    int4   iv = inst[base + m];
    float4 tv = tmk [base + m];
    const float4* ep = emb + ((base + (size_t)m) << 2);
    float4 e0 = ep[0], e1 = ep[1], e2 = ep[2], e3 = ep[3];

    float acc0 = 0.f, acc1 = 0.f;
    for (int it = 1; it < iters; it++) {
        const int mn = m - stride;
        int4   ivn = inst[base + mn];
        float4 tvn = tmk [base + mn];
        const float4* en = emb + ((base + (size_t)mn) << 2);
        float4 n0 = en[0], n1 = en[1], n2 = en[2], n3 = en[3];

        PASS2_PX(iv.x, tv.x, e0, acc0);
        PASS2_PX(iv.y, tv.y, e1, acc1);
        PASS2_PX(iv.z, tv.z, e2, acc0);
        PASS2_PX(iv.w, tv.w, e3, acc1);

        iv = ivn; tv = tvn;
        e0 = n0; e1 = n1; e2 = n2; e3 = n3;
        m = mn;
    }
    PASS2_PX(iv.x, tv.x, e0, acc0);
    PASS2_PX(iv.y, tv.y, e1, acc1);
    PASS2_PX(iv.z, tv.z, e2, acc0);
    PASS2_PX(iv.w, tv.w, e3, acc1);

    float v = wredf(acc0 + acc1);
    if ((threadIdx.x & 31u) == 0) atomicAdd(&g_loss, v);
}

// ---------------- finalize ---------------------------------------------------
__global__ void k_fin(float* out) {
    if (threadIdx.x == 0) {
        float misc = 0.f;
        for (int b = 0; b < NBATCH; b++) misc += g_misc[b];
        out[0] = g_loss + misc * (1.0f / 16.0f);
    }
}

// ---------------- launch -----------------------------------------------------
static int pick_gx(int occ, int nsm) {
    const int divs[8] = {80, 50, 40, 25, 20, 16, 10, 8};  // divisors of 400
    int slots = (occ < 1 ? 1 : occ) * nsm;
    for (int i = 0; i < 8; i++)
        if (NBATCH * divs[i] <= slots) return divs[i];
    return 8;
}

extern "C" void kernel_launch(void* const* d_in, const int* in_sizes, int n_in,
                              void* d_out, int out_size) {
    (void)in_sizes; (void)n_in; (void)out_size;
    const float4* emb  = (const float4*)d_in[0];
    const int4*   inst = (const int4*)  d_in[1];
    const float4* ker  = (const float4*)d_in[2];
    const float4* tmk  = (const float4*)d_in[3];
    float*        out  = (float*)d_out;

    int nsm = 152;
    cudaDeviceGetAttribute(&nsm, cudaDevAttrMultiProcessorCount, 0);
    int occ1 = 0, occ2 = 0;
    cudaOccupancyMaxActiveBlocksPerMultiprocessor(&occ1, k_pass1, 256, 0);
    cudaOccupancyMaxActiveBlocksPerMultiprocessor(&occ2, k_pass2, 256, 0);
    int gx1 = pick_gx(occ1, nsm);
    int gx2 = pick_gx(occ2, nsm);

    k_zero<<<1, 512>>>();
    k_pass1<<<dim3(gx1, NBATCH), 256>>>((const ulonglong2*)emb, inst, ker, tmk);
    k_mid<<<1, 128>>>();
    k_pass2<<<dim3(gx2, NBATCH), 256>>>(emb, inst, tmk);
    k_fin<<<1, 32>>>(out);
}